// round 11
// baseline (speedup 1.0000x reference)
#include <cuda_runtime.h>
#include <cstdint>
#include <math.h>

// Problem constants
#define NN   8
#define MM   4
#define KK   256
#define CGC  64
#define HW   4096          // 64*64
#define TPB  512

// Output layout: concat(q_out, code, logit) as float32
#define Q_ELEMS    (NN*MM*KK*HW)     // 33,554,432
#define CODE_ELEMS (NN*MM*HW)        // 131,072
#define OFF_CODE   Q_ELEMS
#define OFF_LOGIT  (Q_ELEMS + CODE_ELEMS)

// SMEM layout (floats): xs[64][32] | ls[32][260]  (ls is [position][k])
#define LS_STRIDE 260
#define XS_FLOATS (64*32)                   // 2048
#define LS_FLOATS (32*LS_STRIDE)            // 8320
#define SMEM_FLOATS (XS_FLOATS + LS_FLOATS)
#define SMEM_BYTES  (SMEM_FLOATS * 4)       // 41,472 B -> 3 CTAs/SM fits easily

// W transposed to [m][c][k] once by prep kernel (256 KB scratch; L2-resident)
__device__ float Wt_g[MM][CGC][KK];

// ---- packed f32x2 helpers (sm_103a FFMA2 — ptxas never emits this from C++) ----
#define FMA_F32X2(d, a, b, c) \
    asm("fma.rn.f32x2 %0, %1, %2, %3;" : "=l"(d) : "l"(a), "l"(b), "l"(c))
#define PACK_F32X2(out, lo, hi) \
    asm("mov.b64 %0, {%1, %2};" : "=l"(out) : "r"(lo), "r"(hi))
#define UNPACK_F32X2(lo, hi, in) \
    asm("mov.b64 {%0, %1}, %2;" : "=f"(lo), "=f"(hi) : "l"(in))

__device__ __forceinline__ uint32_t tf_rotl(uint32_t x, int d) {
    return __funnelshift_l(x, x, d);
}

// order-preserving float <-> u32 (for REDUX-based float max)
__device__ __forceinline__ uint32_t ford(float v) {
    uint32_t b = __float_as_uint(v);
    return (b & 0x80000000u) ? ~b : (b | 0x80000000u);
}
__device__ __forceinline__ float fdec(uint32_t o) {
    uint32_t b = (o & 0x80000000u) ? (o ^ 0x80000000u) : ~o;
    return __uint_as_float(b);
}

// JAX threefry2x32, key=(0,42), counter hi=0, partitionable: draw = o0^o1.
__device__ __forceinline__ uint32_t threefry_bits(uint32_t cnt) {
    const uint32_t ks1 = 42u;
    const uint32_t ks2 = 0x1BD11BDAu ^ 42u;   // 0x1BD11BF0
    uint32_t x0 = 0u;
    uint32_t x1 = cnt + ks1;
#define TFR(r) { x0 += x1; x1 = tf_rotl(x1, r); x1 ^= x0; }
    TFR(13) TFR(15) TFR(26) TFR(6)
    x0 += ks1; x1 += ks2 + 1u;
    TFR(17) TFR(29) TFR(16) TFR(24)
    x0 += ks2; x1 += 0u + 2u;
    TFR(13) TFR(15) TFR(26) TFR(6)
    x0 += 0u;  x1 += ks1 + 3u;
    TFR(17) TFR(29) TFR(16) TFR(24)
    x0 += ks1; x1 += ks2 + 4u;
    TFR(13) TFR(15) TFR(26) TFR(6)
    x0 += ks2; x1 += 0u + 5u;
#undef TFR
    return x0 ^ x1;
}

// Exact (round-1) gumbel with precise logf — only for warp-uniform near-tie fallback.
__device__ __noinline__ float exact_gumbel(uint32_t cnt) {
    uint32_t bits = threefry_bits(cnt);
    float u = __uint_as_float((bits >> 9) | 0x3f800000u) - 1.0f;
    u = fmaxf(u, 1.17549435e-38f);
    return -logf(-logf(u));
}

__global__ void transpose_w_kernel(const float* __restrict__ w) {
    int i = blockIdx.x * 256 + threadIdx.x;   // over M*K*CG = 65536
    int c = i & 63;
    int km = i >> 6;
    int k = km & 255;
    int m = km >> 8;
    Wt_g[m][c][k] = w[i];
}

union F4U64 { float4 f4; unsigned long long u[2]; };

__global__ void __launch_bounds__(TPB, 3)
mcq_kernel(const float* __restrict__ x,
           float* __restrict__ out)
{
    extern __shared__ float smem[];
    float* xs = smem;                    // [64][32]
    float* ls = xs + XS_FLOATS;          // [32 pos][260]  ls[p][k]
    __shared__ int code_s[32];

    const int b    = blockIdx.x;
    const int tile = b & 127;            // 128 tiles of 32 positions
    const int nm   = b >> 7;
    const int n    = nm >> 2;
    const int m    = nm & 3;
    const int hw_base = tile * 32;
    const int t    = threadIdx.x;
    const int lane = t & 31;
    const int wid  = t >> 5;             // 0..15

    // ---- load x tile (64 ch x 32 pos): one LDG.128 + STS.128 per thread ----
    const float* xb = x + ((size_t)(n * 256 + m * 64)) * HW + hw_base;
    {
        int c = t >> 3, p4 = t & 7;
        ((float4*)xs)[t] = *(const float4*)(xb + (size_t)c * HW + p4 * 4);
    }
    __syncthreads();

    // ---- GEMM: 256 k x 32 pos; thread = (4 k) x (4 pos), packed f32x2 over pos ----
    const int pg = t & 7;                // pos group: positions pg*4..pg*4+3
    const int kq = t >> 3;               // 0..63: k = kq*4..kq*4+3
    unsigned long long accp[2][4];       // [pair jp = pos(2jp,2jp+1)][i = k]
#pragma unroll
    for (int jp = 0; jp < 2; jp++)
#pragma unroll
        for (int i = 0; i < 4; i++) accp[jp][i] = 0ull;

    const float4* wptr = reinterpret_cast<const float4*>(&Wt_g[m][0][kq * 4]);
    const float* xrow = xs + pg * 4;
#pragma unroll 8
    for (int c = 0; c < 64; c++) {
        float4 wv = __ldg(wptr + c * 64);            // one LDG.128 per c-iter
        F4U64 ua;
        ua.f4 = *(const float4*)(xrow + c * 32);     // one LDS.128 per c-iter
        unsigned long long xp[2] = {ua.u[0], ua.u[1]};
        unsigned long long wp[4];
        PACK_F32X2(wp[0], __float_as_uint(wv.x), __float_as_uint(wv.x));
        PACK_F32X2(wp[1], __float_as_uint(wv.y), __float_as_uint(wv.y));
        PACK_F32X2(wp[2], __float_as_uint(wv.z), __float_as_uint(wv.z));
        PACK_F32X2(wp[3], __float_as_uint(wv.w), __float_as_uint(wv.w));
#pragma unroll
        for (int jp = 0; jp < 2; jp++)
#pragma unroll
            for (int i = 0; i < 4; i++)
                FMA_F32X2(accp[jp][i], wp[i], xp[jp], accp[jp][i]);
    }

    // ---- unpack accumulators ----
    float acc[4][4];                     // [j = pos][i = k]
#pragma unroll
    for (int jp = 0; jp < 2; jp++)
#pragma unroll
        for (int i = 0; i < 4; i++)
            UNPACK_F32X2(acc[2 * jp][i], acc[2 * jp + 1][i], accp[jp][i]);

    // ---- stash logits in smem [p][k] (4x STS.128) ----
#pragma unroll
    for (int j = 0; j < 4; j++) {
        *(float4*)(ls + (pg * 4 + j) * LS_STRIDE + kq * 4) =
            make_float4(acc[j][0], acc[j][1], acc[j][2], acc[j][3]);
    }

    // ---- logit writeout straight from registers (4x STG.128, 4 lines/instr) ----
    const size_t obase = ((size_t)(n * 1024 + m * 256)) * HW + hw_base;
    float* lout = out + OFF_LOGIT + obase + pg * 4;
#pragma unroll
    for (int i = 0; i < 4; i++) {
        int k = kq * 4 + i;
        *(float4*)(lout + (size_t)k * HW) =
            make_float4(acc[0][i], acc[1][i], acc[2][i], acc[3][i]);
    }
    __syncthreads();

    // ---- per-position gumbel argmax; 16 warps x 2 positions; lane owns 8 k ----
    const uint32_t pos0 = (uint32_t)((n * 4 + m) * HW + hw_base);
#pragma unroll
    for (int j = 0; j < 2; j++) {
        const int p = wid * 2 + j;
        const uint32_t cnt_base = ((pos0 + (uint32_t)p) << 8) + (uint32_t)(lane * 8);
        const float* lrow = ls + p * LS_STRIDE;

        // vectorized logit load: 8 consecutive floats per lane (2x LDS.128)
        float4 la = *(const float4*)(lrow + lane * 8);
        float4 lb = *(const float4*)(lrow + lane * 8 + 4);
        float lv[8] = {la.x, la.y, la.z, la.w, lb.x, lb.y, lb.z, lb.w};

        // incremental branchless top-2
        float v1 = -1e30f, v2 = -1e30f;
        int   k1 = 0;
#pragma unroll
        for (int q = 0; q < 8; q++) {
            uint32_t bits = threefry_bits(cnt_base + (uint32_t)q);
            float u  = __uint_as_float((bits >> 9) | 0x3f800000u) - 1.0f;
            float w1 = 1.0f - u;                     // exact in fp32
            // 3-term log1p poly: -log(u) = w1 + w1^2/2 + w1^3/3 (rel err <= w1^3/4)
            float Ep = w1 * fmaf(w1, fmaf(w1, 0.33333334f, 0.5f), 1.0f);
            float El = -__logf(fmaxf(u, 1.17549435e-38f));
            float E  = (w1 < 0.015625f) ? Ep : El;   // predicated select
            float v  = lv[q] - __logf(E);
            v2 = fmaxf(v2, fminf(v, v1));            // new second-best
            if (v > v1) { k1 = lane * 8 + q; v1 = v; }  // ascending k => first-max
        }

        // argmax via REDUX: max ordered-value, then min index among ties
        uint32_t o1   = ford(v1);
        uint32_t omax = __reduce_max_sync(0xffffffffu, o1);
        uint32_t cand = (o1 == omax) ? (uint32_t)k1 : 0xffffffffu;
        int   bk   = (int)__reduce_min_sync(0xffffffffu, cand);
        float vmax = fdec(omax);

        // global second-best: losing lanes contribute v1, winning lane its v2
        float s   = (k1 == bk) ? v2 : v1;
        float v2g = fdec(__reduce_max_sync(0xffffffffu, ford(s)));

        if (vmax - v2g < 1e-4f) {
            // warp-uniform rare fallback: exact recompute of ALL 256 values
            float bv = -1e30f;
            int   bi = 0;
#pragma unroll
            for (int q = 0; q < 8; q++) {
                float v = exact_gumbel(cnt_base + (uint32_t)q) + lv[q];
                if (v > bv) { bv = v; bi = lane * 8 + q; }
            }
            uint32_t ob  = ford(bv);
            uint32_t obm = __reduce_max_sync(0xffffffffu, ob);
            uint32_t cb  = (ob == obm) ? (uint32_t)bi : 0xffffffffu;
            bk = (int)__reduce_min_sync(0xffffffffu, cb);
        }

        if (lane == 0) code_s[p] = bk;
    }
    __syncthreads();

    // ---- q_out writeout: 1.0f at hot index, 0 elsewhere (hot==(1+p)-p to 2^-23) ----
    const int g = t & 7;                  // fixed 4-position group per thread
    const int c0 = code_s[g * 4 + 0], c1 = code_s[g * 4 + 1],
              c2 = code_s[g * 4 + 2], c3 = code_s[g * 4 + 3];
    float* qout = out + obase + g * 4;
#pragma unroll
    for (int r = 0; r < 4; r++) {
        int k = (r * 512 + t) >> 3;       // 256 k values, 4 per thread
        *(float4*)(qout + (size_t)k * HW) =
            make_float4(k == c0 ? 1.f : 0.f, k == c1 ? 1.f : 0.f,
                        k == c2 ? 1.f : 0.f, k == c3 ? 1.f : 0.f);
    }
    // ---- code writeout (as float) ----
    if (wid == 0) {
        out[OFF_CODE + (size_t)pos0 + lane] = (float)code_s[lane];
    }
}

extern "C" void kernel_launch(void* const* d_in, const int* in_sizes, int n_in,
                              void* d_out, int out_size)
{
    const float* x = (const float*)d_in[0];
    const float* w = (const float*)d_in[1];
    float* out = (float*)d_out;

    transpose_w_kernel<<<256, 256>>>(w);
    dim3 grid(NN * MM * (HW / 32));   // 4096 blocks
    mcq_kernel<<<grid, TPB, SMEM_BYTES>>>(x, out);
}

// round 12
// speedup vs baseline: 1.1661x; 1.1661x over previous
#include <cuda_runtime.h>
#include <cstdint>
#include <math.h>

// Problem constants
#define NN   8
#define MM   4
#define KK   256
#define CGC  64
#define HW   4096          // 64*64
#define TPB  256

// Output layout: concat(q_out, code, logit) as float32
#define Q_ELEMS    (NN*MM*KK*HW)     // 33,554,432
#define CODE_ELEMS (NN*MM*HW)        // 131,072
#define OFF_CODE   Q_ELEMS
#define OFF_LOGIT  (Q_ELEMS + CODE_ELEMS)

// SMEM layout (floats): xs[64][32] | ls[32][260]  (ls is [position][k])
#define LS_STRIDE 260
#define XS_FLOATS (64*32)                   // 2048
#define LS_FLOATS (32*LS_STRIDE)            // 8320
#define SMEM_FLOATS (XS_FLOATS + LS_FLOATS)
#define SMEM_BYTES  (SMEM_FLOATS * 4)       // 41,472 B -> 4 CTAs/SM (smem-wise)

#define LN2F 0.69314718056f

// W transposed to [m][c][k] once by prep kernel (256 KB scratch; L2-resident)
__device__ float Wt_g[MM][CGC][KK];

// ---- packed f32x2 helpers (sm_103a FFMA2 — ptxas never emits this from C++) ----
#define FMA_F32X2(d, a, b, c) \
    asm("fma.rn.f32x2 %0, %1, %2, %3;" : "=l"(d) : "l"(a), "l"(b), "l"(c))
#define PACK_F32X2(out, lo, hi) \
    asm("mov.b64 %0, {%1, %2};" : "=l"(out) : "r"(lo), "r"(hi))
#define UNPACK_F32X2(lo, hi, in) \
    asm("mov.b64 {%0, %1}, %2;" : "=f"(lo), "=f"(hi) : "l"(in))

__device__ __forceinline__ uint32_t tf_rotl(uint32_t x, int d) {
    return __funnelshift_l(x, x, d);
}

// order-preserving float <-> u32 (for REDUX-based float max)
__device__ __forceinline__ uint32_t ford(float v) {
    uint32_t b = __float_as_uint(v);
    return (b & 0x80000000u) ? ~b : (b | 0x80000000u);
}
__device__ __forceinline__ float fdec(uint32_t o) {
    uint32_t b = (o & 0x80000000u) ? (o ^ 0x80000000u) : ~o;
    return __uint_as_float(b);
}

// JAX threefry2x32, key=(0,42), counter hi=0, partitionable: draw = o0^o1.
__device__ __forceinline__ uint32_t threefry_bits(uint32_t cnt) {
    const uint32_t ks1 = 42u;
    const uint32_t ks2 = 0x1BD11BDAu ^ 42u;   // 0x1BD11BF0
    uint32_t x0 = 0u;
    uint32_t x1 = cnt + ks1;
#define TFR(r) { x0 += x1; x1 = tf_rotl(x1, r); x1 ^= x0; }
    TFR(13) TFR(15) TFR(26) TFR(6)
    x0 += ks1; x1 += ks2 + 1u;
    TFR(17) TFR(29) TFR(16) TFR(24)
    x0 += ks2; x1 += 0u + 2u;
    TFR(13) TFR(15) TFR(26) TFR(6)
    x0 += 0u;  x1 += ks1 + 3u;
    TFR(17) TFR(29) TFR(16) TFR(24)
    x0 += ks1; x1 += ks2 + 4u;
    TFR(13) TFR(15) TFR(26) TFR(6)
    x0 += ks2; x1 += 0u + 5u;
#undef TFR
    return x0 ^ x1;
}

// Exact (round-1) gumbel with precise logf — only for warp-uniform near-tie fallback.
__device__ __noinline__ float exact_gumbel(uint32_t cnt) {
    uint32_t bits = threefry_bits(cnt);
    float u = __uint_as_float((bits >> 9) | 0x3f800000u) - 1.0f;
    u = fmaxf(u, 1.17549435e-38f);
    return -logf(-logf(u));
}

__global__ void transpose_w_kernel(const float* __restrict__ w) {
    int i = blockIdx.x * 256 + threadIdx.x;   // over M*K*CG = 65536
    int c = i & 63;
    int km = i >> 6;
    int k = km & 255;
    int m = km >> 8;
    Wt_g[m][c][k] = w[i];
}

union F4U64 { float4 f4; unsigned long long u[2]; };

__global__ void __launch_bounds__(TPB, 4)
mcq_kernel(const float* __restrict__ x,
           float* __restrict__ out)
{
    extern __shared__ float smem[];
    float* xs = smem;                    // [64][32]
    float* ls = xs + XS_FLOATS;          // [32 pos][260]  ls[p][k]
    __shared__ int code_s[32];

    const int b    = blockIdx.x;
    const int tile = b & 127;            // 128 tiles of 32 positions
    const int nm   = b >> 7;
    const int n    = nm >> 2;
    const int m    = nm & 3;
    const int hw_base = tile * 32;
    const int t    = threadIdx.x;
    const int lane = t & 31;
    const int wid  = t >> 5;

    // ---- load x tile (64 ch x 32 pos), vectorized: 2x LDG.128 + 2x STS.128 ----
    const float* xb = x + ((size_t)(n * 256 + m * 64)) * HW + hw_base;
#pragma unroll
    for (int i = t; i < 512; i += TPB) {
        int c = i >> 3, p4 = i & 7;
        ((float4*)xs)[i] = *(const float4*)(xb + (size_t)c * HW + p4 * 4);
    }
    __syncthreads();

    // ---- GEMM: 256 k x 32 pos; thread = (4 k) x (8 pos), packed f32x2 over pos ----
    const int pg = t & 3;
    const int kq = t >> 2;
    unsigned long long accp[4][4];       // [pair jp = pos(2jp,2jp+1)][i = k]
#pragma unroll
    for (int jp = 0; jp < 4; jp++)
#pragma unroll
        for (int i = 0; i < 4; i++) accp[jp][i] = 0ull;

    const float4* wptr = reinterpret_cast<const float4*>(&Wt_g[m][0][kq * 4]);
    const float* xrow = xs + pg * 8;
#pragma unroll 8
    for (int c = 0; c < 64; c++) {
        float4 wv = __ldg(wptr + c * 64);            // one LDG.128 per c-iter
        F4U64 ua, ub;
        ua.f4 = *(const float4*)(xrow + c * 32);
        ub.f4 = *(const float4*)(xrow + c * 32 + 4);
        unsigned long long xp[4] = {ua.u[0], ua.u[1], ub.u[0], ub.u[1]};
        unsigned long long wp[4];
        PACK_F32X2(wp[0], __float_as_uint(wv.x), __float_as_uint(wv.x));
        PACK_F32X2(wp[1], __float_as_uint(wv.y), __float_as_uint(wv.y));
        PACK_F32X2(wp[2], __float_as_uint(wv.z), __float_as_uint(wv.z));
        PACK_F32X2(wp[3], __float_as_uint(wv.w), __float_as_uint(wv.w));
#pragma unroll
        for (int jp = 0; jp < 4; jp++)
#pragma unroll
            for (int i = 0; i < 4; i++)
                FMA_F32X2(accp[jp][i], wp[i], xp[jp], accp[jp][i]);
    }

    // ---- unpack accumulators ----
    float acc[8][4];                     // [j = pos][i = k]
#pragma unroll
    for (int jp = 0; jp < 4; jp++)
#pragma unroll
        for (int i = 0; i < 4; i++)
            UNPACK_F32X2(acc[2 * jp][i], acc[2 * jp + 1][i], accp[jp][i]);

    // ---- stash logits in smem [p][k] ----
#pragma unroll
    for (int j = 0; j < 8; j++) {
        *(float4*)(ls + (pg * 8 + j) * LS_STRIDE + kq * 4) =
            make_float4(acc[j][0], acc[j][1], acc[j][2], acc[j][3]);
    }

    // ---- logit writeout straight from registers (8x STG.128, 8 lines/instr) ----
    const size_t obase = ((size_t)(n * 1024 + m * 256)) * HW + hw_base;
    float* lout = out + OFF_LOGIT + obase + pg * 8;
#pragma unroll
    for (int i = 0; i < 4; i++) {
        int k = kq * 4 + i;
        *(float4*)(lout + (size_t)k * HW) =
            make_float4(acc[0][i], acc[1][i], acc[2][i], acc[3][i]);
        *(float4*)(lout + (size_t)k * HW + 4) =
            make_float4(acc[4][i], acc[5][i], acc[6][i], acc[7][i]);
    }
    __syncthreads();

    // ---- per-position gumbel argmax; lane owns k = lane*8..lane*8+7 ----
    const uint32_t pos0 = (uint32_t)((n * 4 + m) * HW + hw_base);
    uint32_t cnt_base = ((pos0 + (uint32_t)(wid * 4)) << 8) + (uint32_t)(lane * 8);
    const float* lrow = ls + (wid * 4) * LS_STRIDE;
#pragma unroll 2
    for (int j = 0; j < 4; j++) {
        // vectorized logit load: 8 consecutive floats per lane (2x LDS.128)
        float4 la = *(const float4*)(lrow + lane * 8);
        float4 lb = *(const float4*)(lrow + lane * 8 + 4);
        float lv[8] = {la.x, la.y, la.z, la.w, lb.x, lb.y, lb.z, lb.w};

        // incremental branchless top-2
        float v1 = -1e30f, v2 = -1e30f;
        int   k1 = 0;
#pragma unroll
        for (int q = 0; q < 8; q++) {
            uint32_t bits = threefry_bits(cnt_base + (uint32_t)q);
            float u  = __uint_as_float((bits >> 9) | 0x3f800000u) - 1.0f;
            float w1 = 1.0f - u;                     // exact in fp32
            // 3-term log1p poly: -log(u) = w1 + w1^2/2 + w1^3/3 (rel err <= w1^3/4)
            float Ep = w1 * fmaf(w1, fmaf(w1, 0.33333334f, 0.5f), 1.0f);
            float El = -__logf(fmaxf(u, 1.17549435e-38f));
            float E  = (w1 < 0.015625f) ? Ep : El;   // predicated select
            float v  = fmaf(-LN2F, __log2f(E), lv[q]);  // lv - log(E), MUFU+FFMA
            v2 = fmaxf(v2, fminf(v, v1));            // new second-best
            if (v > v1) { k1 = lane * 8 + q; v1 = v; }  // ascending k => first-max
        }

        // argmax via REDUX: max ordered-value, then min index among ties
        uint32_t o1   = ford(v1);
        uint32_t omax = __reduce_max_sync(0xffffffffu, o1);
        uint32_t cand = (o1 == omax) ? (uint32_t)k1 : 0xffffffffu;
        int   bk   = (int)__reduce_min_sync(0xffffffffu, cand);
        float vmax = fdec(omax);

        // global second-best: losing lanes contribute v1, winning lane its v2
        float s   = (k1 == bk) ? v2 : v1;
        float v2g = fdec(__reduce_max_sync(0xffffffffu, ford(s)));

        if (vmax - v2g < 1e-4f) {
            // warp-uniform rare fallback: exact recompute of ALL 256 values
            float bv = -1e30f;
            int   bi = 0;
#pragma unroll
            for (int q = 0; q < 8; q++) {
                float v = exact_gumbel(cnt_base + (uint32_t)q) + lv[q];
                if (v > bv) { bv = v; bi = lane * 8 + q; }
            }
            uint32_t ob  = ford(bv);
            uint32_t obm = __reduce_max_sync(0xffffffffu, ob);
            uint32_t cb  = (ob == obm) ? (uint32_t)bi : 0xffffffffu;
            bk = (int)__reduce_min_sync(0xffffffffu, cb);
        }

        if (lane == 0) code_s[wid * 4 + j] = bk;
        cnt_base += 256u;                 // next position
        lrow     += LS_STRIDE;
    }
    __syncthreads();

    // ---- q_out writeout: 1.0f at hot index, 0 elsewhere (hot==(1+p)-p to 2^-23) ----
    const int g = t & 7;                  // fixed 4-position group per thread
    const int c0 = code_s[g * 4 + 0], c1 = code_s[g * 4 + 1],
              c2 = code_s[g * 4 + 2], c3 = code_s[g * 4 + 3];
    float* qout = out + obase + g * 4;
#pragma unroll
    for (int r = 0; r < 8; r++) {
        int k = (r * 256 + t) >> 3;       // 256 k values, 8 per thread
        *(float4*)(qout + (size_t)k * HW) =
            make_float4(k == c0 ? 1.f : 0.f, k == c1 ? 1.f : 0.f,
                        k == c2 ? 1.f : 0.f, k == c3 ? 1.f : 0.f);
    }
    // ---- code writeout (as float) ----
    if (wid == 0) {
        out[OFF_CODE + (size_t)pos0 + lane] = (float)code_s[lane];
    }
}

extern "C" void kernel_launch(void* const* d_in, const int* in_sizes, int n_in,
                              void* d_out, int out_size)
{
    const float* x = (const float*)d_in[0];
    const float* w = (const float*)d_in[1];
    float* out = (float*)d_out;

    transpose_w_kernel<<<256, 256>>>(w);
    dim3 grid(NN * MM * (HW / 32));   // 4096 blocks
    mcq_kernel<<<grid, TPB, SMEM_BYTES>>>(x, out);
}

// round 13
// speedup vs baseline: 1.1900x; 1.0205x over previous
#include <cuda_runtime.h>
#include <cstdint>
#include <math.h>

// Problem constants
#define NN   8
#define MM   4
#define KK   256
#define CGC  64
#define HW   4096          // 64*64
#define TPB  256

// Output layout: concat(q_out, code, logit) as float32
#define Q_ELEMS    (NN*MM*KK*HW)     // 33,554,432
#define CODE_ELEMS (NN*MM*HW)        // 131,072
#define OFF_CODE   Q_ELEMS
#define OFF_LOGIT  (Q_ELEMS + CODE_ELEMS)

// SMEM layout (floats): xs[64][32] | ls[32][260]  (ls is [position][k])
#define LS_STRIDE 260
#define XS_FLOATS (64*32)                   // 2048
#define LS_FLOATS (32*LS_STRIDE)            // 8320
#define SMEM_FLOATS (XS_FLOATS + LS_FLOATS)
#define SMEM_BYTES  (SMEM_FLOATS * 4)       // 41,472 B -> 4 CTAs/SM (smem-wise)

// W transposed to [m][c][k] once by prep kernel (256 KB scratch; L2-resident)
__device__ float Wt_g[MM][CGC][KK];

// ---- packed f32x2 helpers (sm_103a FFMA2 — ptxas never emits this from C++) ----
#define FMA_F32X2(d, a, b, c) \
    asm("fma.rn.f32x2 %0, %1, %2, %3;" : "=l"(d) : "l"(a), "l"(b), "l"(c))
#define PACK_F32X2(out, lo, hi) \
    asm("mov.b64 %0, {%1, %2};" : "=l"(out) : "r"(lo), "r"(hi))
#define UNPACK_F32X2(lo, hi, in) \
    asm("mov.b64 {%0, %1}, %2;" : "=f"(lo), "=f"(hi) : "l"(in))

__device__ __forceinline__ uint32_t tf_rotl(uint32_t x, int d) {
    return __funnelshift_l(x, x, d);
}

// order-preserving float <-> u32 (only used in the rare exact fallback)
__device__ __forceinline__ uint32_t ford(float v) {
    uint32_t b = __float_as_uint(v);
    return (b & 0x80000000u) ? ~b : (b | 0x80000000u);
}

// JAX threefry2x32, key=(0,42), counter hi=0, partitionable: draw = o0^o1.
__device__ __forceinline__ uint32_t threefry_bits(uint32_t cnt) {
    const uint32_t ks1 = 42u;
    const uint32_t ks2 = 0x1BD11BDAu ^ 42u;   // 0x1BD11BF0
    uint32_t x0 = 0u;
    uint32_t x1 = cnt + ks1;
#define TFR(r) { x0 += x1; x1 = tf_rotl(x1, r); x1 ^= x0; }
    TFR(13) TFR(15) TFR(26) TFR(6)
    x0 += ks1; x1 += ks2 + 1u;
    TFR(17) TFR(29) TFR(16) TFR(24)
    x0 += ks2; x1 += 0u + 2u;
    TFR(13) TFR(15) TFR(26) TFR(6)
    x0 += 0u;  x1 += ks1 + 3u;
    TFR(17) TFR(29) TFR(16) TFR(24)
    x0 += ks1; x1 += ks2 + 4u;
    TFR(13) TFR(15) TFR(26) TFR(6)
    x0 += ks2; x1 += 0u + 5u;
#undef TFR
    return x0 ^ x1;
}

// Exact (round-1) gumbel with precise logf — only for warp-uniform near-tie fallback.
__device__ __noinline__ float exact_gumbel(uint32_t cnt) {
    uint32_t bits = threefry_bits(cnt);
    float u = __uint_as_float((bits >> 9) | 0x3f800000u) - 1.0f;
    u = fmaxf(u, 1.17549435e-38f);
    return -logf(-logf(u));
}

__global__ void transpose_w_kernel(const float* __restrict__ w) {
    int i = blockIdx.x * 256 + threadIdx.x;   // over M*K*CG = 65536
    int c = i & 63;
    int km = i >> 6;
    int k = km & 255;
    int m = km >> 8;
    Wt_g[m][c][k] = w[i];
}

union F4U64 { float4 f4; unsigned long long u[2]; };

__global__ void __launch_bounds__(TPB, 4)
mcq_kernel(const float* __restrict__ x,
           float* __restrict__ out)
{
    extern __shared__ float smem[];
    float* xs = smem;                    // [64][32]
    float* ls = xs + XS_FLOATS;          // [32 pos][260]  ls[p][k]
    __shared__ int code_s[32];

    const int b    = blockIdx.x;
    const int tile = b & 127;            // 128 tiles of 32 positions
    const int nm   = b >> 7;
    const int n    = nm >> 2;
    const int m    = nm & 3;
    const int hw_base = tile * 32;
    const int t    = threadIdx.x;
    const int lane = t & 31;
    const int wid  = t >> 5;

    // ---- load x tile (64 ch x 32 pos), vectorized: 2x LDG.128 + 2x STS.128 ----
    const float* xb = x + ((size_t)(n * 256 + m * 64)) * HW + hw_base;
#pragma unroll
    for (int i = t; i < 512; i += TPB) {
        int c = i >> 3, p4 = i & 7;
        ((float4*)xs)[i] = *(const float4*)(xb + (size_t)c * HW + p4 * 4);
    }
    __syncthreads();

    // ---- GEMM: 256 k x 32 pos; thread = (4 k) x (8 pos), packed f32x2 over pos ----
    const int pg = t & 3;
    const int kq = t >> 2;
    unsigned long long accp[4][4];       // [pair jp = pos(2jp,2jp+1)][i = k]
#pragma unroll
    for (int jp = 0; jp < 4; jp++)
#pragma unroll
        for (int i = 0; i < 4; i++) accp[jp][i] = 0ull;

    const float4* wptr = reinterpret_cast<const float4*>(&Wt_g[m][0][kq * 4]);
    const float* xrow = xs + pg * 8;
#pragma unroll 8
    for (int c = 0; c < 64; c++) {
        float4 wv = __ldg(wptr + c * 64);            // one LDG.128 per c-iter
        F4U64 ua, ub;
        ua.f4 = *(const float4*)(xrow + c * 32);
        ub.f4 = *(const float4*)(xrow + c * 32 + 4);
        unsigned long long xp[4] = {ua.u[0], ua.u[1], ub.u[0], ub.u[1]};
        unsigned long long wp[4];
        PACK_F32X2(wp[0], __float_as_uint(wv.x), __float_as_uint(wv.x));
        PACK_F32X2(wp[1], __float_as_uint(wv.y), __float_as_uint(wv.y));
        PACK_F32X2(wp[2], __float_as_uint(wv.z), __float_as_uint(wv.z));
        PACK_F32X2(wp[3], __float_as_uint(wv.w), __float_as_uint(wv.w));
#pragma unroll
        for (int jp = 0; jp < 4; jp++)
#pragma unroll
            for (int i = 0; i < 4; i++)
                FMA_F32X2(accp[jp][i], wp[i], xp[jp], accp[jp][i]);
    }

    // ---- unpack accumulators ----
    float acc[8][4];                     // [j = pos][i = k]
#pragma unroll
    for (int jp = 0; jp < 4; jp++)
#pragma unroll
        for (int i = 0; i < 4; i++)
            UNPACK_F32X2(acc[2 * jp][i], acc[2 * jp + 1][i], accp[jp][i]);

    // ---- stash logits in smem [p][k] ----
#pragma unroll
    for (int j = 0; j < 8; j++) {
        *(float4*)(ls + (pg * 8 + j) * LS_STRIDE + kq * 4) =
            make_float4(acc[j][0], acc[j][1], acc[j][2], acc[j][3]);
    }

    // ---- logit writeout straight from registers (8x STG.128, 8 lines/instr) ----
    const size_t obase = ((size_t)(n * 1024 + m * 256)) * HW + hw_base;
    float* lout = out + OFF_LOGIT + obase + pg * 8;
#pragma unroll
    for (int i = 0; i < 4; i++) {
        int k = kq * 4 + i;
        *(float4*)(lout + (size_t)k * HW) =
            make_float4(acc[0][i], acc[1][i], acc[2][i], acc[3][i]);
        *(float4*)(lout + (size_t)k * HW + 4) =
            make_float4(acc[4][i], acc[5][i], acc[6][i], acc[7][i]);
    }
    __syncthreads();

    // ---- per-position gumbel argmax; lane owns k = lane*8..lane*8+7 ----
    const uint32_t pos0 = (uint32_t)((n * 4 + m) * HW + hw_base);
#pragma unroll 2
    for (int j = 0; j < 4; j++) {
        const int p = wid * 4 + j;
        const uint32_t cnt_base = ((pos0 + (uint32_t)p) << 8) + (uint32_t)(lane * 8);
        const float* lrow = ls + p * LS_STRIDE;

        // vectorized logit load: 8 consecutive floats per lane (2x LDS.128)
        float4 la = *(const float4*)(lrow + lane * 8);
        float4 lb = *(const float4*)(lrow + lane * 8 + 4);
        float lv[8] = {la.x, la.y, la.z, la.w, lb.x, lb.y, lb.z, lb.w};

        // incremental branchless top-2
        float v1 = -1e30f, v2 = -1e30f;
        int   k1 = 0;
#pragma unroll
        for (int q = 0; q < 8; q++) {
            uint32_t bits = threefry_bits(cnt_base + (uint32_t)q);
            float u  = __uint_as_float((bits >> 9) | 0x3f800000u) - 1.0f;
            float w1 = 1.0f - u;                     // exact in fp32
            // 3-term log1p poly: -log(u) = w1 + w1^2/2 + w1^3/3 (rel err <= w1^3/4)
            float Ep = w1 * fmaf(w1, fmaf(w1, 0.33333334f, 0.5f), 1.0f);
            float El = -__logf(fmaxf(u, 1.17549435e-38f));
            float E  = (w1 < 0.015625f) ? Ep : El;   // predicated select
            float v  = lv[q] - __logf(E);
            v2 = fmaxf(v2, fminf(v, v1));            // new second-best
            if (v > v1) { k1 = lane * 8 + q; v1 = v; }  // ascending k => first-max
        }

        // |v| < 50 always, so v+64 > 0: raw float bits of (v+64) are monotone
        // unsigned — no ford/fdec needed. Bias rounding (<= 7.6e-6) is far
        // inside the 1e-4 exact-fallback gate, so decisions match reference.
        uint32_t o1   = __float_as_uint(v1 + 64.0f);
        uint32_t omax = __reduce_max_sync(0xffffffffu, o1);
        uint32_t cand = (o1 == omax) ? (uint32_t)k1 : 0xffffffffu;
        int   bk   = (int)__reduce_min_sync(0xffffffffu, cand);

        // global second-best: losing lanes contribute v1, winning lane its v2
        float s    = (k1 == bk) ? v2 : v1;
        uint32_t osx = __reduce_max_sync(0xffffffffu, __float_as_uint(s + 64.0f));

        if (__uint_as_float(omax) - __uint_as_float(osx) < 1e-4f) {
            // warp-uniform rare fallback: exact recompute of ALL 256 values
            float bv = -1e30f;
            int   bi = 0;
#pragma unroll
            for (int q = 0; q < 8; q++) {
                float v = exact_gumbel(cnt_base + (uint32_t)q) + lv[q];
                if (v > bv) { bv = v; bi = lane * 8 + q; }
            }
            uint32_t ob  = ford(bv);
            uint32_t obm = __reduce_max_sync(0xffffffffu, ob);
            uint32_t cb  = (ob == obm) ? (uint32_t)bi : 0xffffffffu;
            bk = (int)__reduce_min_sync(0xffffffffu, cb);
        }

        if (lane == 0) code_s[p] = bk;
    }
    __syncthreads();

    // ---- q_out writeout: 1.0f at hot index, 0 elsewhere (hot==(1+p)-p to 2^-23) ----
    const int g = t & 7;                  // fixed 4-position group per thread
    const int c0 = code_s[g * 4 + 0], c1 = code_s[g * 4 + 1],
              c2 = code_s[g * 4 + 2], c3 = code_s[g * 4 + 3];
    float* qout = out + obase + g * 4;
#pragma unroll
    for (int r = 0; r < 8; r++) {
        int k = (r * 256 + t) >> 3;       // 256 k values, 8 per thread
        *(float4*)(qout + (size_t)k * HW) =
            make_float4(k == c0 ? 1.f : 0.f, k == c1 ? 1.f : 0.f,
                        k == c2 ? 1.f : 0.f, k == c3 ? 1.f : 0.f);
    }
    // ---- code writeout (as float) ----
    if (wid == 0) {
        out[OFF_CODE + (size_t)pos0 + lane] = (float)code_s[lane];
    }
}

extern "C" void kernel_launch(void* const* d_in, const int* in_sizes, int n_in,
                              void* d_out, int out_size)
{
    const float* x = (const float*)d_in[0];
    const float* w = (const float*)d_in[1];
    float* out = (float*)d_out;

    transpose_w_kernel<<<256, 256>>>(w);
    dim3 grid(NN * MM * (HW / 32));   // 4096 blocks
    mcq_kernel<<<grid, TPB, SMEM_BYTES>>>(x, out);
}